// round 8
// baseline (speedup 1.0000x reference)
#include <cuda_runtime.h>
#include <cuda_bf16.h>
#include <math.h>
#include <stdint.h>

#define BB 8
#define LL 2048
#define MM 2048
#define DD 256
#define OD 1024

#define LT 128      // CTA L rows
#define MT 32       // M tile
#define NTILES 64   // MM / MT

// ---------------------------------------------------------------------------
// Scratch (device globals)
// ---------------------------------------------------------------------------
__device__ __nv_bfloat16 g_xs_hi[BB*LL*DD],  g_xs_lo[BB*LL*DD];
__device__ __nv_bfloat16 g_mem_hi[BB*MM*DD], g_mem_lo[BB*MM*DD];
__device__ float g_indot[BB*LL], g_mbias[BB*MM];
__device__ float g_rowmax[BB*LL];
__device__ float g_gmax[BB], g_Z[BB], g_o2part[BB*32*DD];

// ---------------------------------------------------------------------------
// PTX helpers
// ---------------------------------------------------------------------------
__device__ __forceinline__ uint32_t smem_u32(const void* p) {
    uint32_t a;
    asm("{ .reg .u64 t; cvta.to.shared.u64 t, %1; cvt.u32.u64 %0, t; }" : "=r"(a) : "l"(p));
    return a;
}
__device__ __forceinline__ void ldsm_x4(uint32_t* r, uint32_t a) {
    asm volatile("ldmatrix.sync.aligned.m8n8.x4.shared.b16 {%0,%1,%2,%3}, [%4];"
        : "=r"(r[0]), "=r"(r[1]), "=r"(r[2]), "=r"(r[3]) : "r"(a));
}
__device__ __forceinline__ void ldsm_x4t(uint32_t* r, uint32_t a) {
    asm volatile("ldmatrix.sync.aligned.m8n8.x4.trans.shared.b16 {%0,%1,%2,%3}, [%4];"
        : "=r"(r[0]), "=r"(r[1]), "=r"(r[2]), "=r"(r[3]) : "r"(a));
}
__device__ __forceinline__ void mma16816(float* d, const uint32_t* a, const uint32_t* b) {
    asm volatile("mma.sync.aligned.m16n8k16.row.col.f32.bf16.bf16.f32 "
        "{%0,%1,%2,%3}, {%4,%5,%6,%7}, {%8,%9}, {%0,%1,%2,%3};"
        : "+f"(d[0]), "+f"(d[1]), "+f"(d[2]), "+f"(d[3])
        : "r"(a[0]), "r"(a[1]), "r"(a[2]), "r"(a[3]), "r"(b[0]), "r"(b[1]));
}
__device__ __forceinline__ void split4(float4 v, uint2& hi, uint2& lo) {
    __nv_bfloat16 h0 = __float2bfloat16(v.x), h1 = __float2bfloat16(v.y);
    __nv_bfloat16 h2 = __float2bfloat16(v.z), h3 = __float2bfloat16(v.w);
    __nv_bfloat16 l0 = __float2bfloat16(v.x - __bfloat162float(h0));
    __nv_bfloat16 l1 = __float2bfloat16(v.y - __bfloat162float(h1));
    __nv_bfloat16 l2 = __float2bfloat16(v.z - __bfloat162float(h2));
    __nv_bfloat16 l3 = __float2bfloat16(v.w - __bfloat162float(h3));
    hi.x = (uint32_t)__bfloat16_as_ushort(h0) | ((uint32_t)__bfloat16_as_ushort(h1) << 16);
    hi.y = (uint32_t)__bfloat16_as_ushort(h2) | ((uint32_t)__bfloat16_as_ushort(h3) << 16);
    lo.x = (uint32_t)__bfloat16_as_ushort(l0) | ((uint32_t)__bfloat16_as_ushort(l1) << 16);
    lo.y = (uint32_t)__bfloat16_as_ushort(l2) | ((uint32_t)__bfloat16_as_ushort(l3) << 16);
}
__device__ __forceinline__ void packpair(float x, float y, uint32_t& hi, uint32_t& lo) {
    __nv_bfloat16 hx = __float2bfloat16(x), hy = __float2bfloat16(y);
    __nv_bfloat16 lx = __float2bfloat16(x - __bfloat162float(hx));
    __nv_bfloat16 ly = __float2bfloat16(y - __bfloat162float(hy));
    hi = (uint32_t)__bfloat16_as_ushort(hx) | ((uint32_t)__bfloat16_as_ushort(hy) << 16);
    lo = (uint32_t)__bfloat16_as_ushort(lx) | ((uint32_t)__bfloat16_as_ushort(ly) << 16);
}
__device__ __forceinline__ float fast_exp(float x) {
    x = fmaxf(x, -80.0f);
    float y = x * 1.4426950408889634f;
    float nf = y + 12582912.0f;
    int   i  = __float_as_int(nf);
    float n  = nf - 12582912.0f;
    float f  = y - n;
    float p = 1.5403530e-4f;
    p = fmaf(p, f, 1.3333558e-3f);
    p = fmaf(p, f, 9.6181291e-3f);
    p = fmaf(p, f, 5.5504109e-2f);
    p = fmaf(p, f, 2.4022651e-1f);
    p = fmaf(p, f, 6.9314718e-1f);
    p = fmaf(p, f, 1.0f);
    return p * __int_as_float((i - 0x4B3FFF81) << 23);
}
__device__ __forceinline__ void cp_async16(uint32_t dst, const void* src) {
    asm volatile("cp.async.cg.shared.global [%0], [%1], 16;" :: "r"(dst), "l"(src) : "memory");
}
__device__ __forceinline__ void cp_commit() {
    asm volatile("cp.async.commit_group;" ::: "memory");
}
template <int N>
__device__ __forceinline__ void cp_wait() {
    asm volatile("cp.async.wait_group %0;" :: "n"(N) : "memory");
}

// ---------------------------------------------------------------------------
// smem layout (bytes)
// ---------------------------------------------------------------------------
#define SXS 264                 // row stride in halves
#define SX_HI  0                // 128 x 264 halves = 67584
#define SX_LO  67584
#define SM_B   135168           // mem tiles: 2 bufs x (hi 16896 + lo 16896)
#define SM_BUF 33792
#define SM_LOO 16896
#define SMB    202752           // mbias 2048 f32 = 8192
#define FUSED_SMEM 210944

// ---------------------------------------------------------------------------
// dots
// ---------------------------------------------------------------------------
__global__ void dots_kernel(const float* __restrict__ inp, const float* __restrict__ mem,
                            const float* __restrict__ mask, const float* __restrict__ wi,
                            const float* __restrict__ wm) {
    int row = blockIdx.x * 8 + (threadIdx.x >> 5);
    int lane = threadIdx.x & 31;
    bool isMem = row >= BB * LL;
    int r = isMem ? row - BB * LL : row;
    const float* src = (isMem ? mem : inp) + (size_t)r * DD;
    const float* w = isMem ? wm : wi;
    float s = 0.f;
    #pragma unroll
    for (int k = 0; k < 8; k++) { int d = lane + 32 * k; s = fmaf(src[d], w[d], s); }
    #pragma unroll
    for (int o = 16; o; o >>= 1) s += __shfl_xor_sync(0xffffffffu, s, o);
    if (lane == 0) {
        if (isMem) g_mbias[r] = s - 1e30f * (1.0f - mask[r]);
        else       g_indot[r] = s;
    }
}

// ---------------------------------------------------------------------------
// conv: hi/lo bf16 split of xs = input*ds and memory
// ---------------------------------------------------------------------------
__global__ void conv_kernel(const float* __restrict__ inp, const float* __restrict__ mem,
                            const float* __restrict__ ds) {
    const int N4 = BB * LL * DD / 4;
    int i = blockIdx.x * 256 + threadIdx.x;
    bool isMem = i >= N4;
    int j = isMem ? i - N4 : i;
    float4 x = ((const float4*)(isMem ? mem : inp))[j];
    if (!isMem) {
        float4 s = ((const float4*)ds)[j & (DD / 4 - 1)];
        x.x *= s.x; x.y *= s.y; x.z *= s.z; x.w *= s.w;
    }
    uint2 hv, lv;
    split4(x, hv, lv);
    ((uint2*)(isMem ? g_mem_hi : g_xs_hi))[j] = hv;
    ((uint2*)(isMem ? g_mem_lo : g_xs_lo))[j] = lv;
}

// ---------------------------------------------------------------------------
// FUSED flash kernel. CTA = 128 L-rows, 64 M-tiles of 32.
// ---------------------------------------------------------------------------
__global__ void __launch_bounds__(256, 1) fused_kernel(const float* __restrict__ inp,
                                                       float* __restrict__ out) {
    extern __shared__ char sm[];
    const uint32_t s0 = smem_u32(sm);
    const int tid = threadIdx.x, lane = tid & 31, warp = tid >> 5;
    const int lbase = blockIdx.x * LT, b = blockIdx.y;

    // ---- async prologue ----
    #pragma unroll
    for (int j = 0; j < 16; j++) {
        int i = tid + j * 256;
        int row = i >> 5, c = i & 31;
        size_t src = (size_t)(b * LL + lbase + row) * DD + c * 8;
        uint32_t d = (uint32_t)(row * SXS + c * 8) * 2;
        cp_async16(s0 + SX_HI + d, g_xs_hi + src);
        cp_async16(s0 + SX_LO + d, g_xs_lo + src);
    }
    #pragma unroll
    for (int j = 0; j < 2; j++) {
        int i = tid + j * 256;
        cp_async16(s0 + SMB + i * 16, g_mbias + b * MM + i * 4);
    }
    auto LOADMEM = [&](int t, int buf) {
        uint32_t base = s0 + SM_B + (uint32_t)buf * SM_BUF;
        #pragma unroll
        for (int j = 0; j < 4; j++) {
            int i = tid + j * 256;
            int row = i >> 5, c = i & 31;
            size_t src = (size_t)(b * MM + t * MT + row) * DD + c * 8;
            uint32_t d = (uint32_t)(row * SXS + c * 8) * 2;
            cp_async16(base + d, g_mem_hi + src);
            cp_async16(base + SM_LOO + d, g_mem_lo + src);
        }
    };
    LOADMEM(0, 0);
    cp_commit();
    LOADMEM(1, 1);
    cp_commit();
    cp_wait<1>();
    __syncthreads();

    const int q = lane >> 3, lr = lane & 7;      // q: 0..3 lane-group
    const int rr = lane >> 2, cc = (lane & 3) * 2;
    const int wl = warp * 16;
    const float idot0 = g_indot[b * LL + lbase + wl + rr];
    const float idot1 = g_indot[b * LL + lbase + wl + rr + 8];
    const float* smb = (const float*)(sm + SMB);

    float O[32][4];
    #pragma unroll
    for (int nt = 0; nt < 32; nt++) { O[nt][0] = 0.f; O[nt][1] = 0.f; O[nt][2] = 0.f; O[nt][3] = 0.f; }
    float m0 = -INFINITY, m1 = -INFINITY, z0 = 0.f, z1 = 0.f;

    for (int t = 0; t < NTILES; t++) {
        const uint32_t mh = s0 + SM_B + (uint32_t)(t & 1) * SM_BUF;
        const uint32_t mlo = mh + SM_LOO;

        // ---- S = xs . mem^T (3-pass bf16), x4 ldmatrix ----
        float scf[4][4];
        #pragma unroll
        for (int nt = 0; nt < 4; nt++) { scf[nt][0]=0.f; scf[nt][1]=0.f; scf[nt][2]=0.f; scf[nt][3]=0.f; }
        #pragma unroll
        for (int ks = 0; ks < 16; ks++) {
            uint32_t ao = (uint32_t)((wl + (q & 1) * 8 + lr) * SXS + ks * 16 + (q >> 1) * 8) * 2;
            uint32_t ah[4], al[4];
            ldsm_x4(ah, s0 + SX_HI + ao);
            ldsm_x4(al, s0 + SX_LO + ao);
            // B x4 non-trans: matrices (nt, b0),(nt, b1),(nt+1, b0),(nt+1, b1)
            // lane-group g: row = p*16 + (g>>1)*8 + lr, col = ks*16 + (g&1)*8
            uint32_t bh0[4], bh1[4], bl0[4], bl1[4];
            uint32_t bo0 = (uint32_t)(((q >> 1) * 8 + lr) * SXS + ks * 16 + (q & 1) * 8) * 2;
            uint32_t bo1 = bo0 + (uint32_t)(16 * SXS) * 2;
            ldsm_x4(bh0, mh + bo0);
            ldsm_x4(bh1, mh + bo1);
            ldsm_x4(bl0, mlo + bo0);
            ldsm_x4(bl1, mlo + bo1);
            mma16816(scf[0], ah, bh0);     mma16816(scf[1], ah, bh0 + 2);
            mma16816(scf[2], ah, bh1);     mma16816(scf[3], ah, bh1 + 2);
            mma16816(scf[0], ah, bl0);     mma16816(scf[1], ah, bl0 + 2);
            mma16816(scf[2], ah, bl1);     mma16816(scf[3], ah, bl1 + 2);
            mma16816(scf[0], al, bh0);     mma16816(scf[1], al, bh0 + 2);
            mma16816(scf[2], al, bh1);     mma16816(scf[3], al, bh1 + 2);
        }

        // ---- bias + online softmax ----
        #pragma unroll
        for (int nt = 0; nt < 4; nt++) {
            int col = t * MT + nt * 8 + cc;
            float b0 = smb[col], b1 = smb[col + 1];
            scf[nt][0] += idot0 + b0; scf[nt][1] += idot0 + b1;
            scf[nt][2] += idot1 + b0; scf[nt][3] += idot1 + b1;
        }
        float tm0 = -INFINITY, tm1 = -INFINITY;
        #pragma unroll
        for (int nt = 0; nt < 4; nt++) {
            tm0 = fmaxf(tm0, fmaxf(scf[nt][0], scf[nt][1]));
            tm1 = fmaxf(tm1, fmaxf(scf[nt][2], scf[nt][3]));
        }
        #pragma unroll
        for (int x = 1; x <= 2; x <<= 1) {
            tm0 = fmaxf(tm0, __shfl_xor_sync(0xffffffffu, tm0, x));
            tm1 = fmaxf(tm1, __shfl_xor_sync(0xffffffffu, tm1, x));
        }
        float mn0 = fmaxf(m0, tm0), mn1 = fmaxf(m1, tm1);
        float sc0 = __expf(m0 - mn0), sc1 = __expf(m1 - mn1);
        m0 = mn0; m1 = mn1;
        float lz0 = 0.f, lz1 = 0.f;
        #pragma unroll
        for (int nt = 0; nt < 4; nt++) {
            scf[nt][0] = __expf(scf[nt][0] - m0);
            scf[nt][1] = __expf(scf[nt][1] - m0);
            scf[nt][2] = __expf(scf[nt][2] - m1);
            scf[nt][3] = __expf(scf[nt][3] - m1);
            lz0 += scf[nt][0] + scf[nt][1];
            lz1 += scf[nt][2] + scf[nt][3];
        }
        z0 = z0 * sc0 + lz0;
        z1 = z1 * sc1 + lz1;
        // rescale O only if some lane's max actually moved (corr != 1)
        bool need = !__all_sync(0xffffffffu, (sc0 == 1.0f) && (sc1 == 1.0f));
        if (need) {
            #pragma unroll
            for (int nt = 0; nt < 32; nt++) {
                O[nt][0] *= sc0; O[nt][1] *= sc0;
                O[nt][2] *= sc1; O[nt][3] *= sc1;
            }
        }

        // ---- pack P into A-fragments ----
        uint32_t ph[2][4], pl[2][4];
        #pragma unroll
        for (int j2 = 0; j2 < 2; j2++) {
            packpair(scf[2*j2][0],   scf[2*j2][1],   ph[j2][0], pl[j2][0]);
            packpair(scf[2*j2][2],   scf[2*j2][3],   ph[j2][1], pl[j2][1]);
            packpair(scf[2*j2+1][0], scf[2*j2+1][1], ph[j2][2], pl[j2][2]);
            packpair(scf[2*j2+1][2], scf[2*j2+1][3], ph[j2][3], pl[j2][3]);
        }

        // ---- PV: O += P . mem (3-pass), x4-trans ldmatrix (2 n-tiles/load) ----
        #pragma unroll
        for (int ks = 0; ks < 2; ks++) {
            #pragma unroll
            for (int np = 0; np < 16; np++) {
                // matrices: (k-half q&1, col np*16 + (q>>1)*8)
                uint32_t bo = (uint32_t)((ks * 16 + (q & 1) * 8 + lr) * SXS + np * 16 + (q >> 1) * 8) * 2;
                uint32_t bh4[4], bl4[4];
                ldsm_x4t(bh4, mh + bo);
                ldsm_x4t(bl4, mlo + bo);
                mma16816(O[2*np],   ph[ks], bh4);
                mma16816(O[2*np],   ph[ks], bl4);
                mma16816(O[2*np],   pl[ks], bh4);
                mma16816(O[2*np+1], ph[ks], bh4 + 2);
                mma16816(O[2*np+1], ph[ks], bl4 + 2);
                mma16816(O[2*np+1], pl[ks], bh4 + 2);
            }
        }

        __syncthreads();
        if (t + 2 < NTILES) LOADMEM(t + 2, t & 1);
        cp_commit();
        cp_wait<1>();
        __syncthreads();
    }

    // ---- epilogue ----
    #pragma unroll
    for (int x = 1; x <= 2; x <<= 1) {
        z0 += __shfl_xor_sync(0xffffffffu, z0, x);
        z1 += __shfl_xor_sync(0xffffffffu, z1, x);
    }
    float inv0 = 1.0f / z0, inv1 = 1.0f / z1;
    if ((lane & 3) == 0) {
        g_rowmax[b * LL + lbase + wl + rr] = m0;
        g_rowmax[b * LL + lbase + wl + rr + 8] = m1;
    }
    size_t grow0 = (size_t)(b * LL + lbase + wl + rr);
    size_t grow1 = grow0 + 8;
    float* ob0 = out + grow0 * OD;
    float* ob1 = out + grow1 * OD;
    const float* xi0 = inp + grow0 * DD;
    const float* xi1 = inp + grow1 * DD;
    #pragma unroll
    for (int nt = 0; nt < 32; nt++) {
        int d = nt * 8 + cc;
        float2 xv0 = *(const float2*)(xi0 + d);
        float2 xv1 = *(const float2*)(xi1 + d);
        float2 o0 = make_float2(O[nt][0] * inv0, O[nt][1] * inv0);
        float2 o1 = make_float2(O[nt][2] * inv1, O[nt][3] * inv1);
        *(float2*)(ob0 + d)          = xv0;
        *(float2*)(ob0 + DD + d)     = o0;
        *(float2*)(ob0 + 2 * DD + d) = make_float2(xv0.x * o0.x, xv0.y * o0.y);
        *(float2*)(ob1 + d)          = xv1;
        *(float2*)(ob1 + DD + d)     = o1;
        *(float2*)(ob1 + 2 * DD + d) = make_float2(xv1.x * o1.x, xv1.y * o1.y);
    }
}

// ---------------------------------------------------------------------------
// output_two path
// ---------------------------------------------------------------------------
__global__ void c0_kernel() {
    int b = blockIdx.x, tid = threadIdx.x;
    __shared__ float red[256];
    float m = -INFINITY;
    for (int l = tid; l < LL; l += 256) m = fmaxf(m, g_rowmax[b * LL + l]);
    red[tid] = m; __syncthreads();
    for (int s = 128; s; s >>= 1) { if (tid < s) red[tid] = fmaxf(red[tid], red[tid + s]); __syncthreads(); }
    float gmax = red[0]; __syncthreads();
    float z = 0.f;
    for (int l = tid; l < LL; l += 256) z += fast_exp(g_rowmax[b * LL + l] - gmax);
    red[tid] = z; __syncthreads();
    for (int s = 128; s; s >>= 1) { if (tid < s) red[tid] += red[tid + s]; __syncthreads(); }
    if (tid == 0) { g_gmax[b] = gmax; g_Z[b] = red[0]; }
}

__global__ void c1_kernel(const float* __restrict__ inp) {
    int b = blockIdx.y, sblk = blockIdx.x, tid = threadIdx.x;
    __shared__ float ws[64];
    int l0 = sblk * 64;
    if (tid < 64)
        ws[tid] = fast_exp(g_rowmax[b * LL + l0 + tid] - g_gmax[b]) * (1.0f / g_Z[b]);
    __syncthreads();
    float acc = 0.f;
    const float* xp = inp + ((size_t)b * LL + l0) * DD + tid;
    #pragma unroll 4
    for (int l = 0; l < 64; l++) acc = fmaf(ws[l], xp[(size_t)l * DD], acc);
    g_o2part[(b * 32 + sblk) * DD + tid] = acc;
}

__global__ void c2_kernel(float* __restrict__ out) {
    int b = blockIdx.y, tid = threadIdx.x;
    __shared__ float o2s[256];
    float a = 0.f;
    #pragma unroll
    for (int s = 0; s < 32; s++) a += g_o2part[(b * 32 + s) * DD + tid];
    o2s[tid] = a; __syncthreads();
    int lbase = blockIdx.x * 16;
    for (int rr = 0; rr < 16; rr++) {
        size_t ob = ((size_t)(b * LL + lbase + rr)) * OD;
        out[ob + 3 * DD + tid] = o2s[tid] * out[ob + DD + tid];
    }
}

// ---------------------------------------------------------------------------
extern "C" void kernel_launch(void* const* d_in, const int* in_sizes, int n_in,
                              void* d_out, int out_size) {
    const float* inp  = (const float*)d_in[0];
    const float* mem  = (const float*)d_in[1];
    const float* mask = (const float*)d_in[2];
    const float* wi   = (const float*)d_in[3];
    const float* wm   = (const float*)d_in[4];
    const float* ds   = (const float*)d_in[5];
    float* out = (float*)d_out;

    cudaFuncSetAttribute(fused_kernel, cudaFuncAttributeMaxDynamicSharedMemorySize, FUSED_SMEM);

    dots_kernel<<<(BB * (LL + MM)) / 8, 256>>>(inp, mem, mask, wi, wm);
    conv_kernel<<<2 * (BB * LL * DD / 4) / 256, 256>>>(inp, mem, ds);
    fused_kernel<<<dim3(LL / LT, BB), 256, FUSED_SMEM>>>(inp, out);
    c0_kernel<<<BB, 256>>>();
    c1_kernel<<<dim3(LL / 64, BB), 256>>>(inp);
    c2_kernel<<<dim3(LL / 16, BB), 256>>>(out);
}